// round 1
// baseline (speedup 1.0000x reference)
#include <cuda_runtime.h>
#include <math.h>

#define NB   32
#define SQ   512
#define DIM  512
#define K2   1024
#define OFF  (NB * SQ * DIM)   // 8388608 — offset of attention_weights in d_out

// Scratch (allocation-free rule: __device__ globals)
__device__ float g_scores[NB * SQ * SQ];   // 33.5 MB
__device__ float g_ctx[NB * SQ * DIM];     // 33.5 MB

#define BM 128
#define BN 128
#define BK 8
#define LDA (BM + 4)   // pad → conflict-free transposed STS

// ---------------------------------------------------------------------------
// Kernel 1: scores[b] = Q[b] @ E[b]^T * scale   (NT GEMM, M=N=512, K=512)
// ---------------------------------------------------------------------------
__global__ __launch_bounds__(256) void scores_kernel(
    const float* __restrict__ Q, const float* __restrict__ E)
{
    __shared__ float As[BK][LDA];
    __shared__ float Bs[BK][LDA];
    const int b  = blockIdx.z;
    const float* A  = Q + (size_t)b * SQ * DIM;
    const float* Bm = E + (size_t)b * SQ * DIM;
    float* C = g_scores + (size_t)b * SQ * SQ;
    const int m0 = blockIdx.y * BM, n0 = blockIdx.x * BN;
    const int tid = threadIdx.x;
    const int tx = tid & 15, ty = tid >> 4;
    const int lr = tid >> 1;          // 0..127
    const int lk = (tid & 1) * 4;     // 0 or 4

    float acc[8][8] = {};
    for (int k0 = 0; k0 < DIM; k0 += BK) {
        float4 av = *(const float4*)(A  + (size_t)(m0 + lr) * DIM + k0 + lk);
        float4 bv = *(const float4*)(Bm + (size_t)(n0 + lr) * DIM + k0 + lk);
        As[lk+0][lr]=av.x; As[lk+1][lr]=av.y; As[lk+2][lr]=av.z; As[lk+3][lr]=av.w;
        Bs[lk+0][lr]=bv.x; Bs[lk+1][lr]=bv.y; Bs[lk+2][lr]=bv.z; Bs[lk+3][lr]=bv.w;
        __syncthreads();
        #pragma unroll
        for (int k = 0; k < BK; k++) {
            float4 a0 = *(const float4*)&As[k][ty*8];
            float4 a1 = *(const float4*)&As[k][ty*8+4];
            float4 b0 = *(const float4*)&Bs[k][tx*8];
            float4 b1 = *(const float4*)&Bs[k][tx*8+4];
            float ar[8] = {a0.x,a0.y,a0.z,a0.w,a1.x,a1.y,a1.z,a1.w};
            float br[8] = {b0.x,b0.y,b0.z,b0.w,b1.x,b1.y,b1.z,b1.w};
            #pragma unroll
            for (int i = 0; i < 8; i++)
                #pragma unroll
                for (int j = 0; j < 8; j++)
                    acc[i][j] += ar[i] * br[j];
        }
        __syncthreads();
    }
    const float scale = 0.04419417382415922f;  // 1/sqrt(512)
    #pragma unroll
    for (int i = 0; i < 8; i++) {
        int m = m0 + ty*8 + i;
        float4* crow = (float4*)(C + (size_t)m * SQ + n0 + tx*8);
        float4 c0 = {acc[i][0]*scale, acc[i][1]*scale, acc[i][2]*scale, acc[i][3]*scale};
        float4 c1 = {acc[i][4]*scale, acc[i][5]*scale, acc[i][6]*scale, acc[i][7]*scale};
        crow[0] = c0; crow[1] = c1;
    }
}

// ---------------------------------------------------------------------------
// Kernel 2: row softmax, g_scores -> attention_weights (d_out + OFF)
// ---------------------------------------------------------------------------
__global__ __launch_bounds__(256) void softmax_kernel(float* __restrict__ wout)
{
    __shared__ float redm[8];
    __shared__ float reds[8];
    const int row = blockIdx.x;                 // 0 .. NB*SQ-1
    const float* s = g_scores + (size_t)row * SQ;
    float* w = wout + (size_t)row * SQ;
    const int tid = threadIdx.x;

    float v0 = s[tid], v1 = s[tid + 256];
    float m = fmaxf(v0, v1);
    #pragma unroll
    for (int o = 16; o > 0; o >>= 1) m = fmaxf(m, __shfl_xor_sync(0xffffffffu, m, o));
    if ((tid & 31) == 0) redm[tid >> 5] = m;
    __syncthreads();
    if (tid < 32) {
        float t = (tid < 8) ? redm[tid] : -INFINITY;
        #pragma unroll
        for (int o = 4; o > 0; o >>= 1) t = fmaxf(t, __shfl_xor_sync(0xffffffffu, t, o));
        if (tid == 0) redm[0] = t;
    }
    __syncthreads();
    m = redm[0];

    float e0 = __expf(v0 - m), e1 = __expf(v1 - m);
    float sum = e0 + e1;
    #pragma unroll
    for (int o = 16; o > 0; o >>= 1) sum += __shfl_xor_sync(0xffffffffu, sum, o);
    if ((tid & 31) == 0) reds[tid >> 5] = sum;
    __syncthreads();
    if (tid < 32) {
        float t = (tid < 8) ? reds[tid] : 0.0f;
        #pragma unroll
        for (int o = 4; o > 0; o >>= 1) t += __shfl_xor_sync(0xffffffffu, t, o);
        if (tid == 0) reds[0] = t;
    }
    __syncthreads();
    float inv = __frcp_rn(reds[0]);
    w[tid]       = e0 * inv;
    w[tid + 256] = e1 * inv;
}

// ---------------------------------------------------------------------------
// Kernel 3: ctx[b] = weights[b] @ E[b]   (NN GEMM, M=512, K=512, N=512)
// ---------------------------------------------------------------------------
__global__ __launch_bounds__(256) void context_kernel(
    const float* __restrict__ Wt, const float* __restrict__ E)
{
    __shared__ float As[BK][LDA];
    __shared__ float Bs[BK][LDA];
    const int b = blockIdx.z;
    const float* A  = Wt + (size_t)b * SQ * SQ;
    const float* Bm = E  + (size_t)b * SQ * DIM;
    float* C = g_ctx + (size_t)b * SQ * DIM;
    const int m0 = blockIdx.y * BM, n0 = blockIdx.x * BN;
    const int tid = threadIdx.x;
    const int tx = tid & 15, ty = tid >> 4;
    const int lr = tid >> 1;
    const int lk = (tid & 1) * 4;
    const int br_ = tid >> 5;          // 0..7  (B-tile row = k)
    const int bc4 = (tid & 31) * 4;    // 0..124

    float acc[8][8] = {};
    for (int k0 = 0; k0 < SQ; k0 += BK) {
        float4 av = *(const float4*)(A + (size_t)(m0 + lr) * SQ + k0 + lk);
        float4 bv = *(const float4*)(Bm + (size_t)(k0 + br_) * DIM + n0 + bc4);
        As[lk+0][lr]=av.x; As[lk+1][lr]=av.y; As[lk+2][lr]=av.z; As[lk+3][lr]=av.w;
        *(float4*)&Bs[br_][bc4] = bv;
        __syncthreads();
        #pragma unroll
        for (int k = 0; k < BK; k++) {
            float4 a0 = *(const float4*)&As[k][ty*8];
            float4 a1 = *(const float4*)&As[k][ty*8+4];
            float4 b0 = *(const float4*)&Bs[k][tx*8];
            float4 b1 = *(const float4*)&Bs[k][tx*8+4];
            float ar[8] = {a0.x,a0.y,a0.z,a0.w,a1.x,a1.y,a1.z,a1.w};
            float br[8] = {b0.x,b0.y,b0.z,b0.w,b1.x,b1.y,b1.z,b1.w};
            #pragma unroll
            for (int i = 0; i < 8; i++)
                #pragma unroll
                for (int j = 0; j < 8; j++)
                    acc[i][j] += ar[i] * br[j];
        }
        __syncthreads();
    }
    #pragma unroll
    for (int i = 0; i < 8; i++) {
        int m = m0 + ty*8 + i;
        float4* crow = (float4*)(C + (size_t)m * DIM + n0 + tx*8);
        float4 c0 = {acc[i][0],acc[i][1],acc[i][2],acc[i][3]};
        float4 c1 = {acc[i][4],acc[i][5],acc[i][6],acc[i][7]};
        crow[0] = c0; crow[1] = c1;
    }
}

// ---------------------------------------------------------------------------
// Kernel 4: out = tanh([Q|ctx] @ W^T + bias) * mask   (NT, M=16384, N=512, K=1024)
// ---------------------------------------------------------------------------
__global__ __launch_bounds__(256) void final_kernel(
    const float* __restrict__ Q, const float* __restrict__ W,
    const float* __restrict__ bias, const float* __restrict__ mask,
    float* __restrict__ out)
{
    __shared__ float As[BK][LDA];
    __shared__ float Bs[BK][LDA];
    const int m0 = blockIdx.y * BM, n0 = blockIdx.x * BN;
    const int b = m0 >> 9;                         // 128 | 512 → tile within one batch
    const int tid = threadIdx.x;
    const int tx = tid & 15, ty = tid >> 4;
    const int lr = tid >> 1;
    const int lk = (tid & 1) * 4;
    const int mloc = (m0 & (SQ - 1)) + lr;          // row within batch

    const float* Qb = Q     + (size_t)b * SQ * DIM;
    const float* Cb = g_ctx + (size_t)b * SQ * DIM;

    float acc[8][8] = {};
    for (int k0 = 0; k0 < K2; k0 += BK) {
        const float* Abase = (k0 < DIM) ? Qb : Cb;
        const int kk = k0 & (DIM - 1);
        float4 av = *(const float4*)(Abase + (size_t)mloc * DIM + kk + lk);
        float4 bv = *(const float4*)(W + (size_t)(n0 + lr) * K2 + k0 + lk);
        As[lk+0][lr]=av.x; As[lk+1][lr]=av.y; As[lk+2][lr]=av.z; As[lk+3][lr]=av.w;
        Bs[lk+0][lr]=bv.x; Bs[lk+1][lr]=bv.y; Bs[lk+2][lr]=bv.z; Bs[lk+3][lr]=bv.w;
        __syncthreads();
        #pragma unroll
        for (int k = 0; k < BK; k++) {
            float4 a0 = *(const float4*)&As[k][ty*8];
            float4 a1 = *(const float4*)&As[k][ty*8+4];
            float4 b0 = *(const float4*)&Bs[k][tx*8];
            float4 b1 = *(const float4*)&Bs[k][tx*8+4];
            float ar[8] = {a0.x,a0.y,a0.z,a0.w,a1.x,a1.y,a1.z,a1.w};
            float br[8] = {b0.x,b0.y,b0.z,b0.w,b1.x,b1.y,b1.z,b1.w};
            #pragma unroll
            for (int i = 0; i < 8; i++)
                #pragma unroll
                for (int j = 0; j < 8; j++)
                    acc[i][j] += ar[i] * br[j];
        }
        __syncthreads();
    }
    #pragma unroll
    for (int i = 0; i < 8; i++) {
        int m = m0 + ty*8 + i;
        float mk = mask[m];
        float4 c0, c1;
        c0.x = tanhf(acc[i][0] + bias[n0+tx*8+0]) * mk;
        c0.y = tanhf(acc[i][1] + bias[n0+tx*8+1]) * mk;
        c0.z = tanhf(acc[i][2] + bias[n0+tx*8+2]) * mk;
        c0.w = tanhf(acc[i][3] + bias[n0+tx*8+3]) * mk;
        c1.x = tanhf(acc[i][4] + bias[n0+tx*8+4]) * mk;
        c1.y = tanhf(acc[i][5] + bias[n0+tx*8+5]) * mk;
        c1.z = tanhf(acc[i][6] + bias[n0+tx*8+6]) * mk;
        c1.w = tanhf(acc[i][7] + bias[n0+tx*8+7]) * mk;
        float4* crow = (float4*)(out + (size_t)m * DIM + n0 + tx*8);
        crow[0] = c0; crow[1] = c1;
    }
}

// ---------------------------------------------------------------------------
extern "C" void kernel_launch(void* const* d_in, const int* in_sizes, int n_in,
                              void* d_out, int out_size)
{
    const float* Q    = (const float*)d_in[0];  // (32, 512, 512)
    const float* E    = (const float*)d_in[1];  // (32, 512, 512)
    const float* mask = (const float*)d_in[2];  // (32, 512, 1)
    const float* W    = (const float*)d_in[3];  // (512, 1024)
    const float* bias = (const float*)d_in[4];  // (512,)
    float* out  = (float*)d_out;                // attention_masked
    float* wout = out + OFF;                    // attention_weights

    dim3 blk(256);
    scores_kernel <<<dim3(SQ/BN, SQ/BM, NB), blk>>>(Q, E);
    softmax_kernel<<<NB * SQ, blk>>>(wout);
    context_kernel<<<dim3(DIM/BN, SQ/BM, NB), blk>>>(wout, E);
    final_kernel  <<<dim3(DIM/BN, (NB*SQ)/BM, 1), blk>>>(Q, W, bias, mask, out);
}

// round 3
// speedup vs baseline: 2.1475x; 2.1475x over previous
#include <cuda_runtime.h>
#include <cuda_bf16.h>
#include <cstdint>
#include <math.h>

#define NB   32
#define SQ   512
#define DIM  512
#define K2   1024
#define OFF  (NB * SQ * DIM)
#define SCALE 0.04419417382415922f

// ---------------------------------------------------------------------------
// Scratch (__device__ globals: allocation-free rule)
// ---------------------------------------------------------------------------
__device__ __align__(256) __nv_bfloat16 gQh[NB*SQ*DIM], gQl[NB*SQ*DIM];
__device__ __align__(256) __nv_bfloat16 gEh[NB*SQ*DIM], gEl[NB*SQ*DIM];
__device__ __align__(256) __nv_bfloat16 gEth[NB*DIM*SQ], gEtl[NB*DIM*SQ]; // E^T [d][s]
__device__ __align__(256) __nv_bfloat16 gPh[NB*SQ*SQ],  gPl[NB*SQ*SQ];   // softmax split
__device__ __align__(256) __nv_bfloat16 gCh[NB*SQ*DIM], gCl[NB*SQ*DIM];  // context split
__device__ __align__(256) __nv_bfloat16 gWh[DIM*K2],    gWl[DIM*K2];
__device__ float g_scores[NB*SQ*SQ];

// ---------------------------------------------------------------------------
// PTX helpers (sm_103-safe: mma.sync / ldmatrix / cp.async only)
// ---------------------------------------------------------------------------
__device__ __forceinline__ uint32_t smem_u32(const void* p) {
    uint32_t a;
    asm("{ .reg .u64 t; cvta.to.shared.u64 t, %1; cvt.u32.u64 %0, t; }" : "=r"(a) : "l"(p));
    return a;
}
__device__ __forceinline__ void cp16(uint32_t s, const void* g) {
    asm volatile("cp.async.cg.shared.global [%0], [%1], 16;" :: "r"(s), "l"(g));
}
#define CP_COMMIT() asm volatile("cp.async.commit_group;" ::: "memory")
#define CP_WAIT1()  asm volatile("cp.async.wait_group 1;" ::: "memory")

__device__ __forceinline__ void ldsm4(uint32_t* r, uint32_t addr) {
    asm volatile("ldmatrix.sync.aligned.m8n8.x4.shared.b16 {%0,%1,%2,%3}, [%4];"
        : "=r"(r[0]), "=r"(r[1]), "=r"(r[2]), "=r"(r[3]) : "r"(addr));
}
__device__ __forceinline__ void mma_bf16(float* d, const uint32_t* a, uint32_t b0, uint32_t b1) {
    asm volatile("mma.sync.aligned.m16n8k16.row.col.f32.bf16.bf16.f32 "
        "{%0,%1,%2,%3}, {%4,%5,%6,%7}, {%8,%9}, {%0,%1,%2,%3};"
        : "+f"(d[0]), "+f"(d[1]), "+f"(d[2]), "+f"(d[3])
        : "r"(a[0]), "r"(a[1]), "r"(a[2]), "r"(a[3]), "r"(b0), "r"(b1));
}

// Swizzled offset inside an 8KB tile (128 rows x 32 bf16 = 64B/row, 128B atoms)
__device__ __forceinline__ uint32_t sw_off(int r, int c) {
    int pr = r >> 1;
    int ic = ((r & 1) << 2) | c;
    return (uint32_t)((pr << 7) + ((ic ^ (pr & 7)) << 4));
}

// ---------------------------------------------------------------------------
// Conversion kernels
// ---------------------------------------------------------------------------
__device__ __forceinline__ void split4(float4 v, __nv_bfloat16* dh, __nv_bfloat16* dl) {
    union { __nv_bfloat16 h[4]; uint2 u; } H, L;
    float f[4] = {v.x, v.y, v.z, v.w};
    #pragma unroll
    for (int j = 0; j < 4; j++) {
        __nv_bfloat16 h = __float2bfloat16(f[j]);
        H.h[j] = h;
        L.h[j] = __float2bfloat16(f[j] - __bfloat162float(h));
    }
    *(uint2*)dh = H.u;
    *(uint2*)dl = L.u;
}

__global__ __launch_bounds__(256) void split_qe_kernel(
    const float* __restrict__ Q, const float* __restrict__ E)
{
    const size_t TOT = (size_t)NB * SQ * DIM;
    size_t i = ((size_t)blockIdx.x * 256 + threadIdx.x) * 4;
    if (i < TOT) split4(*(const float4*)(Q + i),       gQh + i,       gQl + i);
    else         split4(*(const float4*)(E + (i-TOT)), gEh + (i-TOT), gEl + (i-TOT));
}

__global__ __launch_bounds__(256) void split_w_kernel(const float* __restrict__ W)
{
    size_t i = ((size_t)blockIdx.x * 256 + threadIdx.x) * 4;
    split4(*(const float4*)(W + i), gWh + i, gWl + i);
}

__global__ __launch_bounds__(256) void transpose_e_kernel(const float* __restrict__ E)
{
    __shared__ float t[32][33];
    const int b = blockIdx.z;
    const int tx = threadIdx.x, ty = threadIdx.y;       // block (32, 8)
    const int x = blockIdx.x * 32 + tx;                 // d (read)
    const int y0 = blockIdx.y * 32;                     // s base
    const float* Eb = E + (size_t)b * SQ * DIM;
    #pragma unroll
    for (int j = 0; j < 32; j += 8)
        t[ty + j][tx] = Eb[(size_t)(y0 + ty + j) * DIM + x];
    __syncthreads();
    const int s = y0 + tx;
    const int d0 = blockIdx.x * 32;
    __nv_bfloat16* Oh = gEth + (size_t)b * DIM * SQ;
    __nv_bfloat16* Ol = gEtl + (size_t)b * DIM * SQ;
    #pragma unroll
    for (int j = 0; j < 32; j += 8) {
        float f = t[tx][ty + j];
        __nv_bfloat16 h = __float2bfloat16(f);
        Oh[(size_t)(d0 + ty + j) * SQ + s] = h;
        Ol[(size_t)(d0 + ty + j) * SQ + s] = __float2bfloat16(f - __bfloat162float(h));
    }
}

// ---------------------------------------------------------------------------
// Softmax: g_scores -> weights (fp32, d_out+OFF) + bf16 split P
// ---------------------------------------------------------------------------
__global__ __launch_bounds__(256) void softmax_kernel(float* __restrict__ wout)
{
    __shared__ float redm[8], reds[8];
    const int row = blockIdx.x;
    const float* s = g_scores + (size_t)row * SQ;
    float* w = wout + (size_t)row * SQ;
    const int tid = threadIdx.x;

    float v0 = s[tid], v1 = s[tid + 256];
    float m = fmaxf(v0, v1);
    #pragma unroll
    for (int o = 16; o > 0; o >>= 1) m = fmaxf(m, __shfl_xor_sync(0xffffffffu, m, o));
    if ((tid & 31) == 0) redm[tid >> 5] = m;
    __syncthreads();
    if (tid < 32) {
        float t = (tid < 8) ? redm[tid] : -INFINITY;
        #pragma unroll
        for (int o = 4; o > 0; o >>= 1) t = fmaxf(t, __shfl_xor_sync(0xffffffffu, t, o));
        if (tid == 0) redm[0] = t;
    }
    __syncthreads();
    m = redm[0];
    float e0 = __expf(v0 - m), e1 = __expf(v1 - m);
    float sum = e0 + e1;
    #pragma unroll
    for (int o = 16; o > 0; o >>= 1) sum += __shfl_xor_sync(0xffffffffu, sum, o);
    if ((tid & 31) == 0) reds[tid >> 5] = sum;
    __syncthreads();
    if (tid < 32) {
        float t = (tid < 8) ? reds[tid] : 0.0f;
        #pragma unroll
        for (int o = 4; o > 0; o >>= 1) t += __shfl_xor_sync(0xffffffffu, t, o);
        if (tid == 0) reds[0] = t;
    }
    __syncthreads();
    float inv = __frcp_rn(reds[0]);
    float w0 = e0 * inv, w1 = e1 * inv;
    w[tid] = w0; w[tid + 256] = w1;
    size_t o = (size_t)row * SQ;
    __nv_bfloat16 h0 = __float2bfloat16(w0);
    __nv_bfloat16 h1 = __float2bfloat16(w1);
    gPh[o + tid] = h0;       gPl[o + tid]       = __float2bfloat16(w0 - __bfloat162float(h0));
    gPh[o + tid + 256] = h1; gPl[o + tid + 256] = __float2bfloat16(w1 - __bfloat162float(h1));
}

// ---------------------------------------------------------------------------
// mma.sync bf16-split GEMM (K' = 3K expansion: Ah*Bh + Al*Bh + Ah*Bl)
//   128x128 CTA tile, BK=32, 3-stage cp.async, 8 warps (2M x 4N), 64x32 warp tile
// MODE 0: scores  S = Q @ E^T * scale          (batched, K=512)
// MODE 1: context C = P @ Et^T                 (batched, K=512) -> bf16 split
// MODE 2: final   O = tanh([Q|C] @ W^T + b)*mk (flat M=16384, K=1024)
// ---------------------------------------------------------------------------
template <int MODE>
__global__ __launch_bounds__(256, 2) void gemm_kernel(
    const float* __restrict__ bias, const float* __restrict__ mask,
    float* __restrict__ out)
{
    __shared__ __align__(128) char sm[3 * 16384];   // per stage: A 8KB + B 8KB
    const uint32_t sbase = smem_u32(sm);
    const int tid = threadIdx.x;
    const int lane = tid & 31, wid = tid >> 5;
    const int wm = wid & 1, wn = wid >> 1;           // 2 x 4 warps
    const int m0 = blockIdx.y * 128, n0 = blockIdx.x * 128;

    constexpr int K   = (MODE == 2) ? K2 : 512;
    constexpr int KC  = K / 32;                       // chunks per term
    constexpr int NC  = 3 * KC;                       // total chunks
    constexpr int LDA = (MODE == 1) ? SQ : DIM;       // A leading dim (bf16 elems)
    constexpr int LDB = (MODE == 2) ? K2 : ((MODE == 1) ? SQ : DIM);

    size_t offA = 0, offB = 0;
    if constexpr (MODE == 0) { offA = (size_t)blockIdx.z * SQ * DIM; offB = offA; }
    if constexpr (MODE == 1) { offA = (size_t)blockIdx.z * SQ * SQ;
                               offB = (size_t)blockIdx.z * DIM * SQ; }

    // per-thread load coords (2 x 16B vectors per tile)
    const int lr0 = tid >> 2,          lc0 = tid & 3;
    const int lr1 = (tid + 256) >> 2,  lc1 = (tid + 256) & 3;
    const uint32_t sA0 = sw_off(lr0, lc0), sA1 = sw_off(lr1, lc1);

    auto load_chunk = [&](int q, int st) {
        const int term = q / KC;
        const int kk   = (q - term * KC) * 32;
        const __nv_bfloat16 *A_, *B_;
        int ka = kk;
        if constexpr (MODE == 0) {
            A_ = ((term == 1) ? gQl : gQh) + offA;
            B_ = ((term == 2) ? gEl : gEh) + offA;
        } else if constexpr (MODE == 1) {
            A_ = ((term == 1) ? gPl  : gPh)  + offA;
            B_ = ((term == 2) ? gEtl : gEth) + offB;
        } else {
            if (kk < 512) { A_ = (term == 1) ? gQl : gQh; ka = kk; }
            else          { A_ = (term == 1) ? gCl : gCh; ka = kk - 512; }
            B_ = (term == 2) ? gWl : gWh;
        }
        const uint32_t sA = sbase + st * 16384;
        const uint32_t sB = sA + 8192;
        cp16(sA + sA0, A_ + (size_t)(m0 + lr0) * LDA + ka + lc0 * 8);
        cp16(sA + sA1, A_ + (size_t)(m0 + lr1) * LDA + ka + lc1 * 8);
        cp16(sB + sA0, B_ + (size_t)(n0 + lr0) * LDB + kk + lc0 * 8);
        cp16(sB + sA1, B_ + (size_t)(n0 + lr1) * LDB + kk + lc1 * 8);
    };

    float acc[4][4][4];
    #pragma unroll
    for (int i = 0; i < 4; i++)
        #pragma unroll
        for (int j = 0; j < 4; j++)
            #pragma unroll
            for (int v = 0; v < 4; v++) acc[i][j][v] = 0.0f;

    // prologue: stages 0,1
    load_chunk(0, 0); CP_COMMIT();
    load_chunk(1, 1); CP_COMMIT();

    const int lrow = lane & 15;       // ldmatrix row within 16
    const int lch  = lane >> 4;       // 0/1 -> k half (16B chunk)

    for (int c = 0; c < NC; c++) {
        CP_WAIT1();
        __syncthreads();
        if (c + 2 < NC) load_chunk(c + 2, (c + 2) % 3);
        CP_COMMIT();

        const int st = c % 3;
        const uint32_t sA = sbase + st * 16384;
        const uint32_t sB = sA + 8192;
        #pragma unroll
        for (int ks = 0; ks < 2; ks++) {
            uint32_t a[4][4], b[2][4];
            #pragma unroll
            for (int im = 0; im < 4; im++)
                ldsm4(a[im], sA + sw_off(wm*64 + im*16 + lrow, ks*2 + lch));
            #pragma unroll
            for (int jn = 0; jn < 2; jn++)
                ldsm4(b[jn], sB + sw_off(wn*32 + jn*16 + lrow, ks*2 + lch));
            #pragma unroll
            for (int im = 0; im < 4; im++)
                #pragma unroll
                for (int j = 0; j < 4; j++)
                    mma_bf16(acc[im][j], a[im], b[j>>1][j&1], b[j>>1][(j&1)+2]);
        }
    }

    // ---------------- epilogue ----------------
    const int gid = lane >> 2, tig = lane & 3;
    #pragma unroll
    for (int im = 0; im < 4; im++) {
        const int m = m0 + wm*64 + im*16 + gid;       // rows m, m+8
        float mk0 = 0.f, mk1 = 0.f;
        if constexpr (MODE == 2) { mk0 = mask[m]; mk1 = mask[m + 8]; }
        #pragma unroll
        for (int j = 0; j < 4; j++) {
            const int n = n0 + wn*32 + j*8 + tig*2;
            const float* A4 = acc[im][j];
            if constexpr (MODE == 0) {
                float* C = g_scores + (size_t)blockIdx.z * SQ * SQ;
                *(float2*)(C + (size_t)m * SQ + n)       = {A4[0]*SCALE, A4[1]*SCALE};
                *(float2*)(C + (size_t)(m+8) * SQ + n)   = {A4[2]*SCALE, A4[3]*SCALE};
            } else if constexpr (MODE == 1) {
                const size_t base = (size_t)blockIdx.z * SQ * DIM;
                #pragma unroll
                for (int rr = 0; rr < 2; rr++) {
                    const size_t o = base + (size_t)(m + rr*8) * DIM + n;
                    float f0 = A4[rr*2], f1 = A4[rr*2+1];
                    union { __nv_bfloat16 h[2]; uint32_t u; } H, L;
                    __nv_bfloat16 h0 = __float2bfloat16(f0);
                    __nv_bfloat16 h1 = __float2bfloat16(f1);
                    H.h[0] = h0; H.h[1] = h1;
                    L.h[0] = __float2bfloat16(f0 - __bfloat162float(h0));
                    L.h[1] = __float2bfloat16(f1 - __bfloat162float(h1));
                    *(uint32_t*)(gCh + o) = H.u;
                    *(uint32_t*)(gCl + o) = L.u;
                }
            } else {
                const float b0 = bias[n], b1 = bias[n + 1];
                *(float2*)(out + (size_t)m * DIM + n) =
                    {tanhf(A4[0] + b0) * mk0, tanhf(A4[1] + b1) * mk0};
                *(float2*)(out + (size_t)(m+8) * DIM + n) =
                    {tanhf(A4[2] + b0) * mk1, tanhf(A4[3] + b1) * mk1};
            }
        }
    }
}

// ---------------------------------------------------------------------------
extern "C" void kernel_launch(void* const* d_in, const int* in_sizes, int n_in,
                              void* d_out, int out_size)
{
    const float* Q    = (const float*)d_in[0];  // (32, 512, 512)
    const float* E    = (const float*)d_in[1];  // (32, 512, 512)
    const float* mask = (const float*)d_in[2];  // (32, 512, 1)
    const float* W    = (const float*)d_in[3];  // (512, 1024)
    const float* bias = (const float*)d_in[4];  // (512,)
    float* out  = (float*)d_out;
    float* wout = out + OFF;

    split_qe_kernel   <<<16384, 256>>>(Q, E);
    split_w_kernel    <<<512, 256>>>(W);
    transpose_e_kernel<<<dim3(16, 16, 32), dim3(32, 8)>>>(E);

    gemm_kernel<0><<<dim3(4, 4, 32),  256>>>(nullptr, nullptr, nullptr);
    softmax_kernel<<<NB * SQ, 256>>>(wout);
    gemm_kernel<1><<<dim3(4, 4, 32),  256>>>(nullptr, nullptr, nullptr);
    gemm_kernel<2><<<dim3(4, 128, 1), 256>>>(bias, mask, out);
}

// round 4
// speedup vs baseline: 2.4130x; 1.1236x over previous
#include <cuda_runtime.h>
#include <cuda_bf16.h>
#include <cstdint>
#include <math.h>

#define NB   32
#define SQ   512
#define DIM  512
#define K2   1024
#define OFF  (NB * SQ * DIM)
#define SCALE 0.04419417382415922f

// ---------------------------------------------------------------------------
// Scratch (__device__ globals: allocation-free rule)
// ---------------------------------------------------------------------------
__device__ __align__(256) __nv_bfloat16 gQh[NB*SQ*DIM], gQl[NB*SQ*DIM];
__device__ __align__(256) __nv_bfloat16 gEh[NB*SQ*DIM], gEl[NB*SQ*DIM];
__device__ __align__(256) __nv_bfloat16 gEth[NB*DIM*SQ], gEtl[NB*DIM*SQ]; // E^T [d][s]
__device__ __align__(256) __nv_bfloat16 gPh[NB*SQ*SQ],  gPl[NB*SQ*SQ];   // softmax split
__device__ __align__(256) __nv_bfloat16 gCh[NB*SQ*DIM], gCl[NB*SQ*DIM];  // context split
__device__ __align__(256) __nv_bfloat16 gWh[DIM*K2],    gWl[DIM*K2];
__device__ float g_scores[NB*SQ*SQ];

// ---------------------------------------------------------------------------
// PTX helpers (plain-sm_103-safe: mma.sync / ldmatrix / cp.async)
// ---------------------------------------------------------------------------
__device__ __forceinline__ uint32_t smem_u32(const void* p) {
    uint32_t a;
    asm("{ .reg .u64 t; cvta.to.shared.u64 t, %1; cvt.u32.u64 %0, t; }" : "=r"(a) : "l"(p));
    return a;
}
__device__ __forceinline__ void cp16(uint32_t s, const void* g) {
    asm volatile("cp.async.cg.shared.global [%0], [%1], 16;" :: "r"(s), "l"(g));
}
#define CP_COMMIT() asm volatile("cp.async.commit_group;" ::: "memory")
#define CP_WAIT1()  asm volatile("cp.async.wait_group 1;" ::: "memory")

__device__ __forceinline__ void ldsm4(uint32_t* r, uint32_t addr) {
    asm volatile("ldmatrix.sync.aligned.m8n8.x4.shared.b16 {%0,%1,%2,%3}, [%4];"
        : "=r"(r[0]), "=r"(r[1]), "=r"(r[2]), "=r"(r[3]) : "r"(addr));
}
__device__ __forceinline__ void mma_bf16(float* d, const uint32_t* a, uint32_t b0, uint32_t b1) {
    asm volatile("mma.sync.aligned.m16n8k16.row.col.f32.bf16.bf16.f32 "
        "{%0,%1,%2,%3}, {%4,%5,%6,%7}, {%8,%9}, {%0,%1,%2,%3};"
        : "+f"(d[0]), "+f"(d[1]), "+f"(d[2]), "+f"(d[3])
        : "r"(a[0]), "r"(a[1]), "r"(a[2]), "r"(a[3]), "r"(b0), "r"(b1));
}

// SW128 swizzle for 128B rows (64 bf16/row), tile = 128 rows x 128B = 16KB
__device__ __forceinline__ uint32_t sw128(int r, int c16) {
    return (uint32_t)(r * 128 + (((c16) ^ (r & 7)) << 4));
}

// ---------------------------------------------------------------------------
// Conversion kernels
// ---------------------------------------------------------------------------
__device__ __forceinline__ void split4(float4 v, __nv_bfloat16* dh, __nv_bfloat16* dl) {
    union { __nv_bfloat16 h[4]; uint2 u; } H, L;
    float f[4] = {v.x, v.y, v.z, v.w};
    #pragma unroll
    for (int j = 0; j < 4; j++) {
        __nv_bfloat16 h = __float2bfloat16(f[j]);
        H.h[j] = h;
        L.h[j] = __float2bfloat16(f[j] - __bfloat162float(h));
    }
    *(uint2*)dh = H.u;
    *(uint2*)dl = L.u;
}

__global__ __launch_bounds__(256) void split_q_kernel(const float* __restrict__ Q)
{
    size_t i = ((size_t)blockIdx.x * 256 + threadIdx.x) * 4;
    split4(*(const float4*)(Q + i), gQh + i, gQl + i);
}

__global__ __launch_bounds__(256) void split_w_kernel(const float* __restrict__ W)
{
    size_t i = ((size_t)blockIdx.x * 256 + threadIdx.x) * 4;
    split4(*(const float4*)(W + i), gWh + i, gWl + i);
}

// E -> row-major split (gEh/gEl) AND transposed split (gEth/gEtl), one read of E
__global__ __launch_bounds__(256) void split_transpose_e_kernel(const float* __restrict__ E)
{
    __shared__ float t[32][33];
    const int b = blockIdx.z;
    const int tx = threadIdx.x, ty = threadIdx.y;       // block (32, 8)
    const int x = blockIdx.x * 32 + tx;                 // d (read)
    const int y0 = blockIdx.y * 32;                     // s base
    const size_t base = (size_t)b * SQ * DIM;
    const float* Eb = E + base;
    #pragma unroll
    for (int j = 0; j < 32; j += 8) {
        float f = Eb[(size_t)(y0 + ty + j) * DIM + x];
        t[ty + j][tx] = f;
        __nv_bfloat16 h = __float2bfloat16(f);
        size_t o = base + (size_t)(y0 + ty + j) * DIM + x;
        gEh[o] = h;
        gEl[o] = __float2bfloat16(f - __bfloat162float(h));
    }
    __syncthreads();
    const int s = y0 + tx;
    const int d0 = blockIdx.x * 32;
    #pragma unroll
    for (int j = 0; j < 32; j += 8) {
        float f = t[tx][ty + j];
        __nv_bfloat16 h = __float2bfloat16(f);
        size_t o = base + (size_t)(d0 + ty + j) * SQ + s;
        gEth[o] = h;
        gEtl[o] = __float2bfloat16(f - __bfloat162float(h));
    }
}

// ---------------------------------------------------------------------------
// Softmax: g_scores -> weights (fp32, d_out+OFF) + bf16 split P
// ---------------------------------------------------------------------------
__global__ __launch_bounds__(256) void softmax_kernel(float* __restrict__ wout)
{
    __shared__ float redm[8], reds[8];
    const int row = blockIdx.x;
    const float* s = g_scores + (size_t)row * SQ;
    float* w = wout + (size_t)row * SQ;
    const int tid = threadIdx.x;

    float v0 = s[tid], v1 = s[tid + 256];
    float m = fmaxf(v0, v1);
    #pragma unroll
    for (int o = 16; o > 0; o >>= 1) m = fmaxf(m, __shfl_xor_sync(0xffffffffu, m, o));
    if ((tid & 31) == 0) redm[tid >> 5] = m;
    __syncthreads();
    if (tid < 32) {
        float t = (tid < 8) ? redm[tid] : -INFINITY;
        #pragma unroll
        for (int o = 4; o > 0; o >>= 1) t = fmaxf(t, __shfl_xor_sync(0xffffffffu, t, o));
        if (tid == 0) redm[0] = t;
    }
    __syncthreads();
    m = redm[0];
    float e0 = __expf(v0 - m), e1 = __expf(v1 - m);
    float sum = e0 + e1;
    #pragma unroll
    for (int o = 16; o > 0; o >>= 1) sum += __shfl_xor_sync(0xffffffffu, sum, o);
    if ((tid & 31) == 0) reds[tid >> 5] = sum;
    __syncthreads();
    if (tid < 32) {
        float t = (tid < 8) ? reds[tid] : 0.0f;
        #pragma unroll
        for (int o = 4; o > 0; o >>= 1) t += __shfl_xor_sync(0xffffffffu, t, o);
        if (tid == 0) reds[0] = t;
    }
    __syncthreads();
    float inv = __frcp_rn(reds[0]);
    float w0 = e0 * inv, w1 = e1 * inv;
    w[tid] = w0; w[tid + 256] = w1;
    size_t o = (size_t)row * SQ;
    __nv_bfloat16 h0 = __float2bfloat16(w0);
    __nv_bfloat16 h1 = __float2bfloat16(w1);
    gPh[o + tid] = h0;       gPl[o + tid]       = __float2bfloat16(w0 - __bfloat162float(h0));
    gPh[o + tid + 256] = h1; gPl[o + tid + 256] = __float2bfloat16(w1 - __bfloat162float(h1));
}

// ---------------------------------------------------------------------------
// mma.sync bf16-split GEMM (terms: Ah*Bh + Al*Bh + Ah*Bl), 128x128 CTA tile,
// BK=64, 3-stage cp.async pipeline, 8 warps (2M x 4N), 64x32 warp tile.
// All swizzled addresses hoisted; inner loop is ldsm+mma+adds only.
// MODE 0: scores  S = Q @ E^T * scale          (batched, K=512)
// MODE 1: context C = P @ Et^T                 (batched, K=512) -> bf16 split
// MODE 2: final   O = tanh([Q|C] @ W^T + b)*mk (flat M=16384, K=1024)
// ---------------------------------------------------------------------------
#define STG 32768                       // per-stage: A 16KB + B 16KB
#define GEMM_SMEM (3 * STG)

template <int MODE>
__global__ __launch_bounds__(256, 2) void gemm_kernel(
    const float* __restrict__ bias, const float* __restrict__ mask,
    float* __restrict__ out)
{
    extern __shared__ __align__(128) char sm[];
    const uint32_t sbase = smem_u32(sm);
    const int tid = threadIdx.x;
    const int lane = tid & 31, wid = tid >> 5;
    const int wm = wid & 1, wn = wid >> 1;           // 2 x 4 warps
    const int m0 = blockIdx.y * 128, n0 = blockIdx.x * 128;

    constexpr int K   = (MODE == 2) ? K2 : 512;
    constexpr int KC  = K / 64;                      // chunks per term
    constexpr int NC  = 3 * KC;
    constexpr int LDA = (MODE == 1) ? SQ : DIM;
    constexpr int LDB = (MODE == 2) ? K2 : ((MODE == 1) ? SQ : DIM);

    size_t offA = 0, offB = 0;
    if constexpr (MODE == 0) { offA = (size_t)blockIdx.z * SQ * DIM; offB = offA; }
    if constexpr (MODE == 1) { offA = (size_t)blockIdx.z * SQ * SQ;
                               offB = (size_t)blockIdx.z * DIM * SQ; }

    // ---- load-side hoisted coords: thread covers rows {r0, r0+32, +64, +96}, fixed c16
    const int r0  = tid >> 3;
    const int c16 = tid & 7;
    const uint32_t swb = sw128(r0, c16);             // affine: +it*4096 per 32 rows

    auto load_chunk = [&](int q, int st) {
        const int term = q / KC;
        const int kk   = (q - term * KC) * 64;
        const __nv_bfloat16 *A_, *B_;
        int ka = kk;
        if constexpr (MODE == 0) {
            A_ = ((term == 1) ? gQl : gQh) + offA;
            B_ = ((term == 2) ? gEl : gEh) + offB;
        } else if constexpr (MODE == 1) {
            A_ = ((term == 1) ? gPl  : gPh)  + offA;
            B_ = ((term == 2) ? gEtl : gEth) + offB;
        } else {
            if (kk < 512) { A_ = (term == 1) ? gQl : gQh; }
            else          { A_ = (term == 1) ? gCl : gCh; ka = kk - 512; }
            B_ = (term == 2) ? gWl : gWh;
        }
        const __nv_bfloat16* ga = A_ + (size_t)(m0 + r0) * LDA + ka + c16 * 8;
        const __nv_bfloat16* gb = B_ + (size_t)(n0 + r0) * LDB + kk + c16 * 8;
        const uint32_t sA = sbase + (uint32_t)st * STG + swb;
        const uint32_t sB = sA + 16384;
        #pragma unroll
        for (int it = 0; it < 4; it++) {
            cp16(sA + it * 4096, ga + (size_t)it * 32 * LDA);
            cp16(sB + it * 4096, gb + (size_t)it * 32 * LDB);
        }
        CP_COMMIT();
    };

    // ---- mma-side hoisted base addresses (per k-step; +2048 per 16 rows)
    const int lrow = lane & 15, lch = lane >> 4;
    uint32_t aB[4], bB[4];
    #pragma unroll
    for (int ks = 0; ks < 4; ks++) {
        aB[ks] = sbase + sw128(wm * 64 + lrow, ks * 2 + lch);
        bB[ks] = sbase + 16384 + sw128(wn * 32 + lrow, ks * 2 + lch);
    }

    float acc[4][4][4];
    #pragma unroll
    for (int i = 0; i < 4; i++)
        #pragma unroll
        for (int j = 0; j < 4; j++)
            #pragma unroll
            for (int v = 0; v < 4; v++) acc[i][j][v] = 0.0f;

    load_chunk(0, 0);
    load_chunk(1, 1);

    for (int c = 0; c < NC; c++) {
        CP_WAIT1();
        __syncthreads();
        if (c + 2 < NC) load_chunk(c + 2, (c + 2) % 3);
        else            CP_COMMIT();

        const uint32_t soff = (uint32_t)(c % 3) * STG;
        #pragma unroll
        for (int ks = 0; ks < 4; ks++) {
            uint32_t a[4][4], b[2][4];
            const uint32_t ab = aB[ks] + soff, bb = bB[ks] + soff;
            #pragma unroll
            for (int im = 0; im < 4; im++) ldsm4(a[im], ab + im * 2048);
            #pragma unroll
            for (int jn = 0; jn < 2; jn++) ldsm4(b[jn], bb + jn * 2048);
            #pragma unroll
            for (int im = 0; im < 4; im++)
                #pragma unroll
                for (int j = 0; j < 4; j++)
                    mma_bf16(acc[im][j], a[im], b[j>>1][j&1], b[j>>1][(j&1)+2]);
        }
        __syncthreads();
    }

    // ---------------- epilogue ----------------
    const int gid = lane >> 2, tig = lane & 3;
    #pragma unroll
    for (int im = 0; im < 4; im++) {
        const int m = m0 + wm*64 + im*16 + gid;       // rows m, m+8
        float mk0 = 0.f, mk1 = 0.f;
        if constexpr (MODE == 2) { mk0 = mask[m]; mk1 = mask[m + 8]; }
        #pragma unroll
        for (int j = 0; j < 4; j++) {
            const int n = n0 + wn*32 + j*8 + tig*2;
            const float* A4 = acc[im][j];
            if constexpr (MODE == 0) {
                float* C = g_scores + (size_t)blockIdx.z * SQ * SQ;
                *(float2*)(C + (size_t)m * SQ + n)     = {A4[0]*SCALE, A4[1]*SCALE};
                *(float2*)(C + (size_t)(m+8) * SQ + n) = {A4[2]*SCALE, A4[3]*SCALE};
            } else if constexpr (MODE == 1) {
                const size_t base = (size_t)blockIdx.z * SQ * DIM;
                #pragma unroll
                for (int rr = 0; rr < 2; rr++) {
                    const size_t o = base + (size_t)(m + rr*8) * DIM + n;
                    float f0 = A4[rr*2], f1 = A4[rr*2+1];
                    union { __nv_bfloat16 h[2]; uint32_t u; } H, L;
                    __nv_bfloat16 h0 = __float2bfloat16(f0);
                    __nv_bfloat16 h1 = __float2bfloat16(f1);
                    H.h[0] = h0; H.h[1] = h1;
                    L.h[0] = __float2bfloat16(f0 - __bfloat162float(h0));
                    L.h[1] = __float2bfloat16(f1 - __bfloat162float(h1));
                    *(uint32_t*)(gCh + o) = H.u;
                    *(uint32_t*)(gCl + o) = L.u;
                }
            } else {
                const float b0 = bias[n], b1 = bias[n + 1];
                *(float2*)(out + (size_t)m * DIM + n) =
                    {tanhf(A4[0] + b0) * mk0, tanhf(A4[1] + b1) * mk0};
                *(float2*)(out + (size_t)(m+8) * DIM + n) =
                    {tanhf(A4[2] + b0) * mk1, tanhf(A4[3] + b1) * mk1};
            }
        }
    }
}

// ---------------------------------------------------------------------------
extern "C" void kernel_launch(void* const* d_in, const int* in_sizes, int n_in,
                              void* d_out, int out_size)
{
    const float* Q    = (const float*)d_in[0];  // (32, 512, 512)
    const float* E    = (const float*)d_in[1];  // (32, 512, 512)
    const float* mask = (const float*)d_in[2];  // (32, 512, 1)
    const float* W    = (const float*)d_in[3];  // (512, 1024)
    const float* bias = (const float*)d_in[4];  // (512,)
    float* out  = (float*)d_out;
    float* wout = out + OFF;

    static bool attr_done = false;
    if (!attr_done) {
        cudaFuncSetAttribute(gemm_kernel<0>, cudaFuncAttributeMaxDynamicSharedMemorySize, GEMM_SMEM);
        cudaFuncSetAttribute(gemm_kernel<1>, cudaFuncAttributeMaxDynamicSharedMemorySize, GEMM_SMEM);
        cudaFuncSetAttribute(gemm_kernel<2>, cudaFuncAttributeMaxDynamicSharedMemorySize, GEMM_SMEM);
        attr_done = true;
    }

    split_q_kernel          <<<8192, 256>>>(Q);
    split_w_kernel          <<<512, 256>>>(W);
    split_transpose_e_kernel<<<dim3(16, 16, 32), dim3(32, 8)>>>(E);

    gemm_kernel<0><<<dim3(4, 4, 32),  256, GEMM_SMEM>>>(nullptr, nullptr, nullptr);
    softmax_kernel<<<NB * SQ, 256>>>(wout);
    gemm_kernel<1><<<dim3(4, 4, 32),  256, GEMM_SMEM>>>(nullptr, nullptr, nullptr);
    gemm_kernel<2><<<dim3(4, 128, 1), 256, GEMM_SMEM>>>(bias, mask, out);
}

// round 5
// speedup vs baseline: 2.4934x; 1.0333x over previous
#include <cuda_runtime.h>
#include <cuda_bf16.h>
#include <cstdint>
#include <math.h>

#define NB   32
#define SQ   512
#define DIM  512
#define K2   1024
#define OFF  (NB * SQ * DIM)
#define SCALE 0.04419417382415922f

// ---------------------------------------------------------------------------
// Scratch (__device__ globals: allocation-free rule)
// ---------------------------------------------------------------------------
__device__ __align__(256) __nv_bfloat16 gQh[NB*SQ*DIM], gQl[NB*SQ*DIM];
__device__ __align__(256) __nv_bfloat16 gEh[NB*SQ*DIM], gEl[NB*SQ*DIM];
__device__ __align__(256) __nv_bfloat16 gEth[NB*DIM*SQ], gEtl[NB*DIM*SQ]; // E^T [d][s]
__device__ __align__(256) __nv_bfloat16 gPh[NB*SQ*SQ],  gPl[NB*SQ*SQ];   // softmax split
__device__ __align__(256) __nv_bfloat16 gCh[NB*SQ*DIM], gCl[NB*SQ*DIM];  // context split
__device__ __align__(256) __nv_bfloat16 gWh[DIM*K2],    gWl[DIM*K2];
__device__ float g_scores[NB*SQ*SQ];

// ---------------------------------------------------------------------------
// PTX helpers (plain-sm_103-safe: mma.sync / ldmatrix / cp.async)
// ---------------------------------------------------------------------------
__device__ __forceinline__ uint32_t smem_u32(const void* p) {
    uint32_t a;
    asm("{ .reg .u64 t; cvta.to.shared.u64 t, %1; cvt.u32.u64 %0, t; }" : "=r"(a) : "l"(p));
    return a;
}
__device__ __forceinline__ void cp16(uint32_t s, const void* g) {
    asm volatile("cp.async.cg.shared.global [%0], [%1], 16;" :: "r"(s), "l"(g));
}
#define CP_COMMIT() asm volatile("cp.async.commit_group;" ::: "memory")
#define CP_WAIT1()  asm volatile("cp.async.wait_group 1;" ::: "memory")

__device__ __forceinline__ void ldsm4(uint32_t* r, uint32_t addr) {
    asm volatile("ldmatrix.sync.aligned.m8n8.x4.shared.b16 {%0,%1,%2,%3}, [%4];"
        : "=r"(r[0]), "=r"(r[1]), "=r"(r[2]), "=r"(r[3]) : "r"(addr));
}
__device__ __forceinline__ void mma_bf16(float* d, const uint32_t* a, uint32_t b0, uint32_t b1) {
    asm volatile("mma.sync.aligned.m16n8k16.row.col.f32.bf16.bf16.f32 "
        "{%0,%1,%2,%3}, {%4,%5,%6,%7}, {%8,%9}, {%0,%1,%2,%3};"
        : "+f"(d[0]), "+f"(d[1]), "+f"(d[2]), "+f"(d[3])
        : "r"(a[0]), "r"(a[1]), "r"(a[2]), "r"(a[3]), "r"(b0), "r"(b1));
}

// SW128 swizzle for 128B rows (64 bf16/row), tile = 128 rows x 128B = 16KB
__device__ __forceinline__ uint32_t sw128(int r, int c16) {
    return (uint32_t)(r * 128 + (((c16) ^ (r & 7)) << 4));
}

// ---------------------------------------------------------------------------
// Conversion kernels
// ---------------------------------------------------------------------------
__device__ __forceinline__ void split4(float4 v, __nv_bfloat16* dh, __nv_bfloat16* dl) {
    union { __nv_bfloat16 h[4]; uint2 u; } H, L;
    float f[4] = {v.x, v.y, v.z, v.w};
    #pragma unroll
    for (int j = 0; j < 4; j++) {
        __nv_bfloat16 h = __float2bfloat16(f[j]);
        H.h[j] = h;
        L.h[j] = __float2bfloat16(f[j] - __bfloat162float(h));
    }
    *(uint2*)dh = H.u;
    *(uint2*)dl = L.u;
}

__global__ __launch_bounds__(256) void split_q_kernel(const float* __restrict__ Q)
{
    size_t i = ((size_t)blockIdx.x * 256 + threadIdx.x) * 4;
    split4(*(const float4*)(Q + i), gQh + i, gQl + i);
}

__global__ __launch_bounds__(256) void split_w_kernel(const float* __restrict__ W)
{
    size_t i = ((size_t)blockIdx.x * 256 + threadIdx.x) * 4;
    split4(*(const float4*)(W + i), gWh + i, gWl + i);
}

// E -> row-major split (gEh/gEl) AND transposed split (gEth/gEtl), one read of E
__global__ __launch_bounds__(256) void split_transpose_e_kernel(const float* __restrict__ E)
{
    __shared__ float t[32][33];
    const int b = blockIdx.z;
    const int tx = threadIdx.x, ty = threadIdx.y;       // block (32, 8)
    const int x = blockIdx.x * 32 + tx;                 // d (read)
    const int y0 = blockIdx.y * 32;                     // s base
    const size_t base = (size_t)b * SQ * DIM;
    const float* Eb = E + base;
    #pragma unroll
    for (int j = 0; j < 32; j += 8) {
        float f = Eb[(size_t)(y0 + ty + j) * DIM + x];
        t[ty + j][tx] = f;
        __nv_bfloat16 h = __float2bfloat16(f);
        size_t o = base + (size_t)(y0 + ty + j) * DIM + x;
        gEh[o] = h;
        gEl[o] = __float2bfloat16(f - __bfloat162float(h));
    }
    __syncthreads();
    const int s = y0 + tx;
    const int d0 = blockIdx.x * 32;
    #pragma unroll
    for (int j = 0; j < 32; j += 8) {
        float f = t[tx][ty + j];
        __nv_bfloat16 h = __float2bfloat16(f);
        size_t o = base + (size_t)(d0 + ty + j) * SQ + s;
        gEth[o] = h;
        gEtl[o] = __float2bfloat16(f - __bfloat162float(h));
    }
}

// ---------------------------------------------------------------------------
// Softmax: g_scores -> weights (fp32, d_out+OFF) + bf16 split P
// ---------------------------------------------------------------------------
__global__ __launch_bounds__(256) void softmax_kernel(float* __restrict__ wout)
{
    __shared__ float redm[8], reds[8];
    const int row = blockIdx.x;
    const float* s = g_scores + (size_t)row * SQ;
    float* w = wout + (size_t)row * SQ;
    const int tid = threadIdx.x;

    float v0 = s[tid], v1 = s[tid + 256];
    float m = fmaxf(v0, v1);
    #pragma unroll
    for (int o = 16; o > 0; o >>= 1) m = fmaxf(m, __shfl_xor_sync(0xffffffffu, m, o));
    if ((tid & 31) == 0) redm[tid >> 5] = m;
    __syncthreads();
    if (tid < 32) {
        float t = (tid < 8) ? redm[tid] : -INFINITY;
        #pragma unroll
        for (int o = 4; o > 0; o >>= 1) t = fmaxf(t, __shfl_xor_sync(0xffffffffu, t, o));
        if (tid == 0) redm[0] = t;
    }
    __syncthreads();
    m = redm[0];
    float e0 = __expf(v0 - m), e1 = __expf(v1 - m);
    float sum = e0 + e1;
    #pragma unroll
    for (int o = 16; o > 0; o >>= 1) sum += __shfl_xor_sync(0xffffffffu, sum, o);
    if ((tid & 31) == 0) reds[tid >> 5] = sum;
    __syncthreads();
    if (tid < 32) {
        float t = (tid < 8) ? reds[tid] : 0.0f;
        #pragma unroll
        for (int o = 4; o > 0; o >>= 1) t += __shfl_xor_sync(0xffffffffu, t, o);
        if (tid == 0) reds[0] = t;
    }
    __syncthreads();
    float inv = __frcp_rn(reds[0]);
    float w0 = e0 * inv, w1 = e1 * inv;
    w[tid] = w0; w[tid + 256] = w1;
    size_t o = (size_t)row * SQ;
    __nv_bfloat16 h0 = __float2bfloat16(w0);
    __nv_bfloat16 h1 = __float2bfloat16(w1);
    gPh[o + tid] = h0;       gPl[o + tid]       = __float2bfloat16(w0 - __bfloat162float(h0));
    gPh[o + tid + 256] = h1; gPl[o + tid + 256] = __float2bfloat16(w1 - __bfloat162float(h1));
}

// ---------------------------------------------------------------------------
// mma.sync bf16-split GEMM (terms: Ah*Bh + Al*Bh + Ah*Bl), 128x128 CTA tile,
// BK=64, 3-stage cp.async, 4 warps (2M x 2N), 64x64 warp tile (halves smem
// fragment traffic per FLOP vs 64x32).
// MODE 0: scores  S = Q @ E^T * scale          (batched, K=512)
// MODE 1: context C = P @ Et^T                 (batched, K=512) -> bf16 split
// MODE 2: final   O = tanh([Q|C] @ W^T + b)*mk (flat M=16384, K=1024)
// ---------------------------------------------------------------------------
#define STG 32768                       // per-stage: A 16KB + B 16KB
#define GEMM_SMEM (3 * STG)

template <int MODE>
__global__ __launch_bounds__(128, 2) void gemm_kernel(
    const float* __restrict__ bias, const float* __restrict__ mask,
    float* __restrict__ out)
{
    extern __shared__ __align__(128) char sm[];
    const uint32_t sbase = smem_u32(sm);
    const int tid = threadIdx.x;
    const int lane = tid & 31, wid = tid >> 5;
    const int wm = wid & 1, wn = wid >> 1;           // 2 x 2 warps
    const int m0 = blockIdx.y * 128, n0 = blockIdx.x * 128;

    constexpr int K   = (MODE == 2) ? K2 : 512;
    constexpr int KC  = K / 64;                      // chunks per term
    constexpr int NC  = 3 * KC;
    constexpr int LDA = (MODE == 1) ? SQ : DIM;
    constexpr int LDB = (MODE == 2) ? K2 : ((MODE == 1) ? SQ : DIM);

    size_t offA = 0, offB = 0;
    if constexpr (MODE == 0) { offA = (size_t)blockIdx.z * SQ * DIM; offB = offA; }
    if constexpr (MODE == 1) { offA = (size_t)blockIdx.z * SQ * SQ;
                               offB = (size_t)blockIdx.z * DIM * SQ; }

    // ---- load-side: 128 threads cover rows {r0 + 16*it}, fixed 16B col c16
    const int r0  = tid >> 3;            // 0..15
    const int c16 = tid & 7;
    const uint32_t swb = sw128(r0, c16); // +16 rows -> +2048 B (XOR bits invariant)

    auto load_chunk = [&](int q, int st) {
        const int term = q / KC;
        const int kk   = (q - term * KC) * 64;
        const __nv_bfloat16 *A_, *B_;
        int ka = kk;
        if constexpr (MODE == 0) {
            A_ = ((term == 1) ? gQl : gQh) + offA;
            B_ = ((term == 2) ? gEl : gEh) + offB;
        } else if constexpr (MODE == 1) {
            A_ = ((term == 1) ? gPl  : gPh)  + offA;
            B_ = ((term == 2) ? gEtl : gEth) + offB;
        } else {
            if (kk < 512) { A_ = (term == 1) ? gQl : gQh; }
            else          { A_ = (term == 1) ? gCl : gCh; ka = kk - 512; }
            B_ = (term == 2) ? gWl : gWh;
        }
        const __nv_bfloat16* ga = A_ + (size_t)(m0 + r0) * LDA + ka + c16 * 8;
        const __nv_bfloat16* gb = B_ + (size_t)(n0 + r0) * LDB + kk + c16 * 8;
        const uint32_t sA = sbase + (uint32_t)st * STG + swb;
        const uint32_t sB = sA + 16384;
        #pragma unroll
        for (int it = 0; it < 8; it++) {
            cp16(sA + it * 2048, ga + (size_t)it * 16 * LDA);
            cp16(sB + it * 2048, gb + (size_t)it * 16 * LDB);
        }
        CP_COMMIT();
    };

    // ---- mma-side hoisted base addresses
    const int lrow = lane & 15, lch = lane >> 4;
    uint32_t aB[4], bB[4];
    #pragma unroll
    for (int ks = 0; ks < 4; ks++) {
        aB[ks] = sbase + sw128(wm * 64 + lrow, ks * 2 + lch);
        bB[ks] = sbase + 16384 + sw128(wn * 64 + lrow, ks * 2 + lch);
    }

    float acc[4][8][4];
    #pragma unroll
    for (int i = 0; i < 4; i++)
        #pragma unroll
        for (int j = 0; j < 8; j++)
            #pragma unroll
            for (int v = 0; v < 4; v++) acc[i][j][v] = 0.0f;

    load_chunk(0, 0);
    load_chunk(1, 1);

    for (int c = 0; c < NC; c++) {
        CP_WAIT1();
        __syncthreads();
        if (c + 2 < NC) load_chunk(c + 2, (c + 2) % 3);
        else            CP_COMMIT();

        const uint32_t soff = (uint32_t)(c % 3) * STG;
        #pragma unroll
        for (int ks = 0; ks < 4; ks++) {
            uint32_t a[4][4], b[4][4];
            const uint32_t ab = aB[ks] + soff, bb = bB[ks] + soff;
            #pragma unroll
            for (int im = 0; im < 4; im++) ldsm4(a[im], ab + im * 2048);
            #pragma unroll
            for (int jn = 0; jn < 4; jn++) ldsm4(b[jn], bb + jn * 2048);
            #pragma unroll
            for (int im = 0; im < 4; im++)
                #pragma unroll
                for (int j = 0; j < 8; j++)
                    mma_bf16(acc[im][j], a[im], b[j>>1][j&1], b[j>>1][(j&1)+2]);
        }
        __syncthreads();
    }

    // ---------------- epilogue ----------------
    const int gid = lane >> 2, tig = lane & 3;
    #pragma unroll
    for (int im = 0; im < 4; im++) {
        const int m = m0 + wm*64 + im*16 + gid;       // rows m, m+8
        float mk0 = 0.f, mk1 = 0.f;
        if constexpr (MODE == 2) { mk0 = mask[m]; mk1 = mask[m + 8]; }
        #pragma unroll
        for (int j = 0; j < 8; j++) {
            const int n = n0 + wn*64 + j*8 + tig*2;
            const float* A4 = acc[im][j];
            if constexpr (MODE == 0) {
                float* C = g_scores + (size_t)blockIdx.z * SQ * SQ;
                *(float2*)(C + (size_t)m * SQ + n)     = {A4[0]*SCALE, A4[1]*SCALE};
                *(float2*)(C + (size_t)(m+8) * SQ + n) = {A4[2]*SCALE, A4[3]*SCALE};
            } else if constexpr (MODE == 1) {
                const size_t base = (size_t)blockIdx.z * SQ * DIM;
                #pragma unroll
                for (int rr = 0; rr < 2; rr++) {
                    const size_t o = base + (size_t)(m + rr*8) * DIM + n;
                    float f0 = A4[rr*2], f1 = A4[rr*2+1];
                    union { __nv_bfloat16 h[2]; uint32_t u; } H, L;
                    __nv_bfloat16 h0 = __float2bfloat16(f0);
                    __nv_bfloat16 h1 = __float2bfloat16(f1);
                    H.h[0] = h0; H.h[1] = h1;
                    L.h[0] = __float2bfloat16(f0 - __bfloat162float(h0));
                    L.h[1] = __float2bfloat16(f1 - __bfloat162float(h1));
                    *(uint32_t*)(gCh + o) = H.u;
                    *(uint32_t*)(gCl + o) = L.u;
                }
            } else {
                const float b0 = bias[n], b1 = bias[n + 1];
                *(float2*)(out + (size_t)m * DIM + n) =
                    {tanhf(A4[0] + b0) * mk0, tanhf(A4[1] + b1) * mk0};
                *(float2*)(out + (size_t)(m+8) * DIM + n) =
                    {tanhf(A4[2] + b0) * mk1, tanhf(A4[3] + b1) * mk1};
            }
        }
    }
}

// ---------------------------------------------------------------------------
extern "C" void kernel_launch(void* const* d_in, const int* in_sizes, int n_in,
                              void* d_out, int out_size)
{
    const float* Q    = (const float*)d_in[0];  // (32, 512, 512)
    const float* E    = (const float*)d_in[1];  // (32, 512, 512)
    const float* mask = (const float*)d_in[2];  // (32, 512, 1)
    const float* W    = (const float*)d_in[3];  // (512, 1024)
    const float* bias = (const float*)d_in[4];  // (512,)
    float* out  = (float*)d_out;
    float* wout = out + OFF;

    static bool attr_done = false;
    if (!attr_done) {
        cudaFuncSetAttribute(gemm_kernel<0>, cudaFuncAttributeMaxDynamicSharedMemorySize, GEMM_SMEM);
        cudaFuncSetAttribute(gemm_kernel<1>, cudaFuncAttributeMaxDynamicSharedMemorySize, GEMM_SMEM);
        cudaFuncSetAttribute(gemm_kernel<2>, cudaFuncAttributeMaxDynamicSharedMemorySize, GEMM_SMEM);
        attr_done = true;
    }

    split_q_kernel          <<<8192, 256>>>(Q);
    split_w_kernel          <<<512, 256>>>(W);
    split_transpose_e_kernel<<<dim3(16, 16, 32), dim3(32, 8)>>>(E);

    gemm_kernel<0><<<dim3(4, 4, 32),  128, GEMM_SMEM>>>(nullptr, nullptr, nullptr);
    softmax_kernel<<<NB * SQ, 256>>>(wout);
    gemm_kernel<1><<<dim3(4, 4, 32),  128, GEMM_SMEM>>>(nullptr, nullptr, nullptr);
    gemm_kernel<2><<<dim3(4, 128, 1), 128, GEMM_SMEM>>>(bias, mask, out);
}